// round 10
// baseline (speedup 1.0000x reference)
#include <cuda_runtime.h>
#include <cstdint>

// HashGrid encode: 16 levels, F=2, T=2^19, base_res=16, per_level_scale=2.0,
// smoothstep, 2D. Levels 0..5 dense, 6..15 hashed.
//
// v10 = v9 (smem levels 0..2 + pair-merge + shfl-transpose stores) with:
//  (a) smem levels use 4 plain scalar LDS (no parity branch / float4 unpack --
//      LDS gathers are bank-priced, the merge bought nothing and cost regs),
//  (b) __launch_bounds__(256, 5): pin 5 CTAs/SM (51-reg budget) to recover
//      the CTA v9 lost at 56 regs (occ 45.4% -> ~55%).
// v9 lesson: the smem cache DID cut L1 78.7->66 / L2 63->51.5; the loss was
// occupancy+instruction overhead. This keeps the memory win, drops the cost.

#define NLEVELS 16
#define LOG2_T 19
#define TSIZE (1u << LOG2_T)
#define PRIME1 2654435761u

// smem entry bases for levels 0..2 (res 16, 32, 64)
#define S_L0 0
#define S_L1 256
#define S_L2 1280
#define S_TOT 5376   // 256 + 1024 + 4096 float2 entries = 42KB

__global__ __launch_bounds__(256, 5) void hashgrid_encode_kernel(
    const float2* __restrict__ x,          // [N] points in [-1,1]
    const float2* __restrict__ table,      // [16 * T] float2 entries
    float* __restrict__ out,               // [N, 32]
    int n)
{
    __shared__ float2 stab[S_TOT];

    // ---- cooperative fill of levels 0..2 (coalesced float4 copies) ----
    {
        float4* s4 = reinterpret_cast<float4*>(stab);
        const float4* t0 = reinterpret_cast<const float4*>(table);
        const float4* t1 = reinterpret_cast<const float4*>(table + TSIZE);
        const float4* t2 = reinterpret_cast<const float4*>(table + 2u * TSIZE);
        if (threadIdx.x < 128)
            s4[threadIdx.x] = __ldg(t0 + threadIdx.x);
#pragma unroll
        for (int t = 0; t < 2; ++t)
            s4[128 + t * 256 + threadIdx.x] = __ldg(t1 + t * 256 + threadIdx.x);
#pragma unroll
        for (int t = 0; t < 8; ++t)
            s4[640 + t * 256 + threadIdx.x] = __ldg(t2 + t * 256 + threadIdx.x);
    }
    __syncthreads();

    const int lane = threadIdx.x & 31;
    int i = blockIdx.x * blockDim.x + threadIdx.x;
    if (i >= n) return;

    float2 xi = __ldg(&x[i]);
    float x0 = xi.x * 0.5f + 0.5f;
    float x1 = xi.y * 0.5f + 0.5f;

    float acc[2 * NLEVELS];

#pragma unroll
    for (int l = 0; l < NLEVELS; ++l) {
        const unsigned res = 16u << l;                 // power of two
        const float scale = (float)(res - 1u);

        float p0 = x0 * scale + 0.5f;
        float p1 = x1 * scale + 0.5f;
        float fl0 = floorf(p0);
        float fl1 = floorf(p1);
        float fr0 = p0 - fl0;
        float fr1 = p1 - fl1;
        unsigned g0 = (unsigned)(int)fl0;
        unsigned g1 = (unsigned)(int)fl1;

        // smoothstep weights
        float w0 = fr0 * fr0 * (3.0f - 2.0f * fr0);
        float w1 = fr1 * fr1 * (3.0f - 2.0f * fr1);

        unsigned i00, i10, i01, i11;
        if (l <= 5) {
            const unsigned mask = (res * res) - 1u;
            unsigned b0 = g0 + g1 * res;
            unsigned b1 = b0 + res;
            i00 = b0 & mask;        i10 = (b0 + 1u) & mask;
            i01 = b1 & mask;        i11 = (b1 + 1u) & mask;
        } else {
            const unsigned hmask = TSIZE - 1u;
            unsigned hy0 = g1 * PRIME1;
            unsigned hy1 = hy0 + PRIME1;
            i00 = (g0 ^ hy0) & hmask;        i10 = ((g0 + 1u) ^ hy0) & hmask;
            i01 = (g0 ^ hy1) & hmask;        i11 = ((g0 + 1u) ^ hy1) & hmask;
        }

        float2 f00, f10, f01, f11;

        if (l <= 2) {
            // smem-resident level: plain scalar gathers, branch-free.
            const float2* sl = stab + (l == 0 ? S_L0 : (l == 1 ? S_L1 : S_L2));
            f00 = sl[i00]; f10 = sl[i10];
            f01 = sl[i01]; f11 = sl[i11];
        } else if (l <= 5) {
            // dense gmem level: even-x -> i00/i01 provably even, straight unpack.
            const float2* tl = table + (size_t)l * TSIZE;
            if ((g0 & 1u) == 0u) {
                const float4* tl4 = reinterpret_cast<const float4*>(tl);
                float4 v0 = __ldg(tl4 + (i00 >> 1));
                float4 v1 = __ldg(tl4 + (i01 >> 1));
                f00 = make_float2(v0.x, v0.y); f10 = make_float2(v0.z, v0.w);
                f01 = make_float2(v1.x, v1.y); f11 = make_float2(v1.z, v1.w);
            } else {
                f00 = __ldg(tl + i00);
                f10 = __ldg(tl + i10);
                f01 = __ldg(tl + i01);
                f11 = __ldg(tl + i11);
            }
        } else {
            // hashed level: i10 == i00^1 but i00 may be ODD -> conditional swap.
            const float2* tl = table + (size_t)l * TSIZE;
            if ((g0 & 1u) == 0u) {
                const float4* tl4 = reinterpret_cast<const float4*>(tl);
                float4 v0 = __ldg(tl4 + (i00 >> 1));
                float4 v1 = __ldg(tl4 + (i01 >> 1));
                if (i00 & 1u) { f00 = make_float2(v0.z, v0.w); f10 = make_float2(v0.x, v0.y); }
                else          { f00 = make_float2(v0.x, v0.y); f10 = make_float2(v0.z, v0.w); }
                if (i01 & 1u) { f01 = make_float2(v1.z, v1.w); f11 = make_float2(v1.x, v1.y); }
                else          { f01 = make_float2(v1.x, v1.y); f11 = make_float2(v1.z, v1.w); }
            } else {
                f00 = __ldg(tl + i00);
                f10 = __ldg(tl + i10);
                f01 = __ldg(tl + i01);
                f11 = __ldg(tl + i11);
            }
        }

        float c00 = (1.0f - w0) * (1.0f - w1);
        float c10 = w0 * (1.0f - w1);
        float c01 = (1.0f - w0) * w1;
        float c11 = w0 * w1;

        acc[2 * l]     = c00 * f00.x + c10 * f10.x + c01 * f01.x + c11 * f11.x;
        acc[2 * l + 1] = c00 * f00.y + c10 * f10.y + c01 * f01.y + c11 * f11.y;
    }

    const int wbase = i & ~31;   // first point of this warp
    if (wbase + 32 <= n) {
        // 32x32 in-register transpose (xor butterfly, 5 rounds).
#pragma unroll
        for (int step = 1; step < 32; step <<= 1) {
            const bool up = (lane & step) != 0;
#pragma unroll
            for (int t = 0; t < 32; ++t) {
                if ((t & step) == 0) {
                    float lo = acc[t], hi = acc[t + step];
                    float send = up ? lo : hi;
                    float recv = __shfl_xor_sync(0xffffffffu, send, step);
                    if (up) acc[t] = recv; else acc[t + step] = recv;
                }
            }
        }
        // Fully coalesced: each STG.32 writes 128 consecutive bytes (1 line).
        float* ot = out + (size_t)wbase * 32;
#pragma unroll
        for (int p = 0; p < 32; ++p)
            ot[p * 32 + lane] = acc[p];
    } else {
        // tail warp (not hit for N = 524288): per-thread stores
        float4* o4 = reinterpret_cast<float4*>(out + (size_t)i * 32);
#pragma unroll
        for (int k = 0; k < 8; ++k)
            o4[k] = make_float4(acc[4*k], acc[4*k+1], acc[4*k+2], acc[4*k+3]);
    }
}

extern "C" void kernel_launch(void* const* d_in, const int* in_sizes, int n_in,
                              void* d_out, int out_size)
{
    const float2* x     = (const float2*)d_in[0];   // [N,2] float32
    const float2* table = (const float2*)d_in[1];   // [16, T, 2] float32
    float* out          = (float*)d_out;            // [N, 32] float32

    int n = in_sizes[0] / 2;
    int threads = 256;
    int blocks = (n + threads - 1) / threads;
    hashgrid_encode_kernel<<<blocks, threads>>>(x, table, out, n);
}

// round 11
// speedup vs baseline: 1.7050x; 1.7050x over previous
#include <cuda_runtime.h>
#include <cstdint>

// HashGrid encode: 16 levels, F=2, T=2^19, base_res=16, per_level_scale=2.0,
// smoothstep, 2D. Levels 0..5 dense, 6..15 hashed.
//
// v11 = v7 (81.4us: pair-merged gathers + shfl-transposed coalesced stores),
// split into TWO kernels of 8 levels each (channels 0..15 / 16..31).
// Rationale: v7's acc[32] pins 48 regs -> 5 CTAs/SM -> 40 warps, and L1
// (the wavefront wall) idles 21%. Halving acc to 16 floats cuts regs to
// ~36-40 -> 6-7 CTAs -> 48-56 warps, while keeping 8 unrolled levels per
// kernel for ptxas load batching. Stores become 64B half-rows (2 wf/instr,
// +1 wf/pt) via a 16x16 per-half-warp butterfly transpose.
// NO smem (v10: LDS gathers choke MIO), NO launch_bounds pins (R6), NO
// multi-point threads (R3).

#define NLEVELS 16
#define LOG2_T 19
#define TSIZE (1u << LOG2_T)
#define PRIME1 2654435761u

template <int L_BEGIN>
__global__ void hashgrid_half_kernel(
    const float2* __restrict__ x,          // [N] points in [-1,1]
    const float2* __restrict__ table,      // [16 * T] float2 entries
    float* __restrict__ out,               // [N, 32]
    int n)
{
    const int lane = threadIdx.x & 31;
    int i = blockIdx.x * blockDim.x + threadIdx.x;
    if (i >= n) return;

    float2 xi = __ldg(&x[i]);
    float x0 = xi.x * 0.5f + 0.5f;
    float x1 = xi.y * 0.5f + 0.5f;

    float acc[16];

#pragma unroll
    for (int k = 0; k < 8; ++k) {
        const int l = L_BEGIN + k;
        const unsigned res = 16u << l;                 // power of two
        const float scale = (float)(res - 1u);

        float p0 = x0 * scale + 0.5f;
        float p1 = x1 * scale + 0.5f;
        float fl0 = floorf(p0);
        float fl1 = floorf(p1);
        float fr0 = p0 - fl0;
        float fr1 = p1 - fl1;
        unsigned g0 = (unsigned)(int)fl0;
        unsigned g1 = (unsigned)(int)fl1;

        // smoothstep weights
        float w0 = fr0 * fr0 * (3.0f - 2.0f * fr0);
        float w1 = fr1 * fr1 * (3.0f - 2.0f * fr1);

        unsigned i00, i10, i01, i11;
        if (l <= 5) {
            const unsigned mask = (res * res) - 1u;
            unsigned b0 = g0 + g1 * res;
            unsigned b1 = b0 + res;
            i00 = b0 & mask;        i10 = (b0 + 1u) & mask;
            i01 = b1 & mask;        i11 = (b1 + 1u) & mask;
        } else {
            const unsigned hmask = TSIZE - 1u;
            unsigned hy0 = g1 * PRIME1;
            unsigned hy1 = hy0 + PRIME1;
            i00 = (g0 ^ hy0) & hmask;        i10 = ((g0 + 1u) ^ hy0) & hmask;
            i01 = (g0 ^ hy1) & hmask;        i11 = ((g0 + 1u) ^ hy1) & hmask;
        }

        const float2* tl = table + (size_t)l * TSIZE;
        float2 f00, f10, f01, f11;

        if ((g0 & 1u) == 0u) {
            // x even: row corners are adjacent 8B entries -> one aligned float4.
            // Dense levels: i00/i01 provably even. Hashed: may be odd -> swap.
            const float4* tl4 = reinterpret_cast<const float4*>(tl);
            float4 v0 = __ldg(tl4 + (i00 >> 1));
            float4 v1 = __ldg(tl4 + (i01 >> 1));
            if (l <= 5) {
                f00 = make_float2(v0.x, v0.y); f10 = make_float2(v0.z, v0.w);
                f01 = make_float2(v1.x, v1.y); f11 = make_float2(v1.z, v1.w);
            } else {
                if (i00 & 1u) { f00 = make_float2(v0.z, v0.w); f10 = make_float2(v0.x, v0.y); }
                else          { f00 = make_float2(v0.x, v0.y); f10 = make_float2(v0.z, v0.w); }
                if (i01 & 1u) { f01 = make_float2(v1.z, v1.w); f11 = make_float2(v1.x, v1.y); }
                else          { f01 = make_float2(v1.x, v1.y); f11 = make_float2(v1.z, v1.w); }
            }
        } else {
            f00 = __ldg(tl + i00);
            f10 = __ldg(tl + i10);
            f01 = __ldg(tl + i01);
            f11 = __ldg(tl + i11);
        }

        float c00 = (1.0f - w0) * (1.0f - w1);
        float c10 = w0 * (1.0f - w1);
        float c01 = (1.0f - w0) * w1;
        float c11 = w0 * w1;

        acc[2 * k]     = c00 * f00.x + c10 * f10.x + c01 * f01.x + c11 * f11.x;
        acc[2 * k + 1] = c00 * f00.y + c10 * f10.y + c01 * f01.y + c11 * f11.y;
    }

    const int wbase = i & ~31;   // first point of this warp
    if (wbase + 32 <= n) {
        // 16x16 butterfly transpose within each half-warp (steps 1,2,4,8 stay
        // inside a 16-lane group). Before: lane (16h+p) reg c = channel c of
        // point (wbase+16h+p). After: lane (16h+c) reg p = channel c of
        // point (wbase+16h+p).
#pragma unroll
        for (int step = 1; step < 16; step <<= 1) {
            const bool up = (lane & step) != 0;
#pragma unroll
            for (int t = 0; t < 16; ++t) {
                if ((t & step) == 0) {
                    float lo = acc[t], hi = acc[t + step];
                    float send = up ? lo : hi;
                    float recv = __shfl_xor_sync(0xffffffffu, send, step);
                    if (up) acc[t] = recv; else acc[t + step] = recv;
                }
            }
        }
        // Store j: lanes 0..15 write point (wbase+j) channels [2*L_BEGIN..+16),
        // lanes 16..31 write point (wbase+16+j). 64B contiguous per half-warp.
        const int c0 = 2 * L_BEGIN;
        float* ob = out + (size_t)(wbase + (lane >> 4) * 16) * 32 + c0 + (lane & 15);
#pragma unroll
        for (int j = 0; j < 16; ++j)
            ob[j * 32] = acc[j];
    } else {
        // tail warp (not hit for N = 524288)
        float* ot = out + (size_t)i * 32 + 2 * L_BEGIN;
#pragma unroll
        for (int c = 0; c < 16; ++c) ot[c] = acc[c];
    }
}

extern "C" void kernel_launch(void* const* d_in, const int* in_sizes, int n_in,
                              void* d_out, int out_size)
{
    const float2* x     = (const float2*)d_in[0];   // [N,2] float32
    const float2* table = (const float2*)d_in[1];   // [16, T, 2] float32
    float* out          = (float*)d_out;            // [N, 32] float32

    int n = in_sizes[0] / 2;
    int threads = 256;
    int blocks = (n + threads - 1) / threads;
    hashgrid_half_kernel<0><<<blocks, threads>>>(x, table, out, n);
    hashgrid_half_kernel<8><<<blocks, threads>>>(x, table, out, n);
}

// round 12
// speedup vs baseline: 1.8342x; 1.0758x over previous
#include <cuda_runtime.h>
#include <cstdint>

// HashGrid encode: 16 levels, F=2, T=2^19, base_res=16, per_level_scale=2.0,
// smoothstep, 2D. Levels 0..5 dense, 6..15 hashed.
//
// v12 = v11's two 8-level half-kernels FUSED into one launch:
// grid = 2x blocks, blockIdx.x&1 selects the level-half, so dense-half and
// hashed-half CTAs are co-resident on every SM (removes the inter-kernel
// drain + launch overhead that made v11 lose to v7 by 3us, and lets short
// dense CTAs backfill around long hashed CTAs).
// Per-half body identical to v11: 8 unrolled levels, pair-merged gathers
// (conditional swap on hashed levels), 16x16 half-warp butterfly transpose,
// 64B coalesced half-row stores. regs ~40 -> 6 CTAs/SM.

#define NLEVELS 16
#define LOG2_T 19
#define TSIZE (1u << LOG2_T)
#define PRIME1 2654435761u

template <int L_BEGIN>
__device__ __forceinline__ void half_body(
    int i, int lane, float x0, float x1,
    const float2* __restrict__ table,
    float* __restrict__ out, int n)
{
    float acc[16];

#pragma unroll
    for (int k = 0; k < 8; ++k) {
        const int l = L_BEGIN + k;
        const unsigned res = 16u << l;                 // power of two
        const float scale = (float)(res - 1u);

        float p0 = x0 * scale + 0.5f;
        float p1 = x1 * scale + 0.5f;
        float fl0 = floorf(p0);
        float fl1 = floorf(p1);
        float fr0 = p0 - fl0;
        float fr1 = p1 - fl1;
        unsigned g0 = (unsigned)(int)fl0;
        unsigned g1 = (unsigned)(int)fl1;

        // smoothstep weights
        float w0 = fr0 * fr0 * (3.0f - 2.0f * fr0);
        float w1 = fr1 * fr1 * (3.0f - 2.0f * fr1);

        unsigned i00, i10, i01, i11;
        if (l <= 5) {
            const unsigned mask = (res * res) - 1u;
            unsigned b0 = g0 + g1 * res;
            unsigned b1 = b0 + res;
            i00 = b0 & mask;        i10 = (b0 + 1u) & mask;
            i01 = b1 & mask;        i11 = (b1 + 1u) & mask;
        } else {
            const unsigned hmask = TSIZE - 1u;
            unsigned hy0 = g1 * PRIME1;
            unsigned hy1 = hy0 + PRIME1;
            i00 = (g0 ^ hy0) & hmask;        i10 = ((g0 + 1u) ^ hy0) & hmask;
            i01 = (g0 ^ hy1) & hmask;        i11 = ((g0 + 1u) ^ hy1) & hmask;
        }

        const float2* tl = table + (size_t)l * TSIZE;
        float2 f00, f10, f01, f11;

        if ((g0 & 1u) == 0u) {
            // x even: row corners are adjacent 8B entries -> one aligned float4.
            // Dense levels: i00/i01 provably even. Hashed: may be odd -> swap.
            const float4* tl4 = reinterpret_cast<const float4*>(tl);
            float4 v0 = __ldg(tl4 + (i00 >> 1));
            float4 v1 = __ldg(tl4 + (i01 >> 1));
            if (l <= 5) {
                f00 = make_float2(v0.x, v0.y); f10 = make_float2(v0.z, v0.w);
                f01 = make_float2(v1.x, v1.y); f11 = make_float2(v1.z, v1.w);
            } else {
                if (i00 & 1u) { f00 = make_float2(v0.z, v0.w); f10 = make_float2(v0.x, v0.y); }
                else          { f00 = make_float2(v0.x, v0.y); f10 = make_float2(v0.z, v0.w); }
                if (i01 & 1u) { f01 = make_float2(v1.z, v1.w); f11 = make_float2(v1.x, v1.y); }
                else          { f01 = make_float2(v1.x, v1.y); f11 = make_float2(v1.z, v1.w); }
            }
        } else {
            f00 = __ldg(tl + i00);
            f10 = __ldg(tl + i10);
            f01 = __ldg(tl + i01);
            f11 = __ldg(tl + i11);
        }

        float c00 = (1.0f - w0) * (1.0f - w1);
        float c10 = w0 * (1.0f - w1);
        float c01 = (1.0f - w0) * w1;
        float c11 = w0 * w1;

        acc[2 * k]     = c00 * f00.x + c10 * f10.x + c01 * f01.x + c11 * f11.x;
        acc[2 * k + 1] = c00 * f00.y + c10 * f10.y + c01 * f01.y + c11 * f11.y;
    }

    const int wbase = i & ~31;   // first point of this warp
    if (wbase + 32 <= n) {
        // 16x16 butterfly transpose within each half-warp.
#pragma unroll
        for (int step = 1; step < 16; step <<= 1) {
            const bool up = (lane & step) != 0;
#pragma unroll
            for (int t = 0; t < 16; ++t) {
                if ((t & step) == 0) {
                    float lo = acc[t], hi = acc[t + step];
                    float send = up ? lo : hi;
                    float recv = __shfl_xor_sync(0xffffffffu, send, step);
                    if (up) acc[t] = recv; else acc[t + step] = recv;
                }
            }
        }
        // lanes 0..15 -> point (wbase+j) channels [2*L_BEGIN..+16),
        // lanes 16..31 -> point (wbase+16+j). 64B contiguous per half-warp.
        const int c0 = 2 * L_BEGIN;
        float* ob = out + (size_t)(wbase + (lane >> 4) * 16) * 32 + c0 + (lane & 15);
#pragma unroll
        for (int j = 0; j < 16; ++j)
            ob[j * 32] = acc[j];
    } else {
        // tail warp (not hit for N = 524288)
        float* ot = out + (size_t)i * 32 + 2 * L_BEGIN;
#pragma unroll
        for (int c = 0; c < 16; ++c) ot[c] = acc[c];
    }
}

__global__ void hashgrid_fused_kernel(
    const float2* __restrict__ x,          // [N] points in [-1,1]
    const float2* __restrict__ table,      // [16 * T] float2 entries
    float* __restrict__ out,               // [N, 32]
    int n)
{
    const int lane = threadIdx.x & 31;
    const int half = blockIdx.x & 1;       // 0: levels 0..7, 1: levels 8..15
    const int blk  = blockIdx.x >> 1;
    const int i = blk * blockDim.x + threadIdx.x;
    if (i >= n) return;

    float2 xi = __ldg(&x[i]);
    float x0 = xi.x * 0.5f + 0.5f;
    float x1 = xi.y * 0.5f + 0.5f;

    if (half == 0)
        half_body<0>(i, lane, x0, x1, table, out, n);
    else
        half_body<8>(i, lane, x0, x1, table, out, n);
}

extern "C" void kernel_launch(void* const* d_in, const int* in_sizes, int n_in,
                              void* d_out, int out_size)
{
    const float2* x     = (const float2*)d_in[0];   // [N,2] float32
    const float2* table = (const float2*)d_in[1];   // [16, T, 2] float32
    float* out          = (float*)d_out;            // [N, 32] float32

    int n = in_sizes[0] / 2;
    int threads = 256;
    int blocks = (n + threads - 1) / threads;
    hashgrid_fused_kernel<<<2 * blocks, threads>>>(x, table, out, n);
}